// round 1
// baseline (speedup 1.0000x reference)
#include <cuda_runtime.h>
#include <math.h>

// Problem constants
#define BB 2
#define LL 1024
#define DD 512
#define RR (BB * LL)          // 2048 rows
#define TPJ 16                // total planes (NS*PP)
#define NSB 4                 // n sets
#define PPB 4                 // planes per set
#define PDIM 16               // positional planes
#define NCHAN 36              // 16 bank + 4 cross + 16 positional
#define CCH 64                // chunks along L
#define SCH 16                // chunk size (CCH*SCH == LL)
#define HG 256                // g1 hidden

#define PI_F 3.14159265358979323846f

// ---------------- device scratch (static; no allocations) ----------------
__device__ float2 g_S[BB * CCH * NCHAN * DD];   // chunk sums -> exclusive prefixes (18.9 MB)
__device__ float  g_V[RR * DD];                 // V_real = x@v_w + v_b
__device__ float  g_hpre[RR * HG];              // x@g1_w + g1_b (pre-gelu)
__device__ float  g_gate[RR];
__device__ float  g_wg[RR];
__device__ float  g_kph[RR * 40];               // 20 channels x (cos,sin) key phases
__device__ float  g_qph[RR * 40];               // 20 channels x (cos,sin) query phases (weight-scaled)
__device__ float  g_posph[LL * 32];             // 16 channels x (cos,sin)
__device__ float  g_yn[RR * DD];                // layer-normed y

// ---------------- generic tiled SGEMM ----------------
// C[M,N] = A[M,K] @ B[K,N] + bias[N] (+ resid[M,N])
template <bool RESID>
__global__ __launch_bounds__(256) void sgemm_kernel(
    const float* __restrict__ A, const float* __restrict__ B,
    const float* __restrict__ bias, const float* __restrict__ resid,
    float* __restrict__ C, int M, int N, int K)
{
    const int BM = 64, BN = 64, BK = 16, TM = 4, TN = 4;
    __shared__ float As[BK][BM];
    __shared__ float Bs[BK][BN];
    int tid = threadIdx.x;
    int brow = blockIdx.y * BM, bcol = blockIdx.x * BN;
    int tr = (tid / 16) * TM;
    int tc = (tid % 16) * TN;
    float acc[TM][TN];
#pragma unroll
    for (int i = 0; i < TM; i++)
#pragma unroll
        for (int j = 0; j < TN; j++) acc[i][j] = 0.f;

    for (int k0 = 0; k0 < K; k0 += BK) {
#pragma unroll
        for (int i = tid; i < BM * BK; i += 256) {
            int r = i / BK, c = i % BK;
            int gr = brow + r;
            As[c][r] = (gr < M) ? A[gr * K + k0 + c] : 0.f;
        }
#pragma unroll
        for (int i = tid; i < BK * BN; i += 256) {
            int r = i / BN, c = i % BN;
            int gc = bcol + c;
            Bs[r][c] = (gc < N) ? B[(k0 + r) * N + gc] : 0.f;
        }
        __syncthreads();
#pragma unroll
        for (int kk = 0; kk < BK; kk++) {
            float a[TM], bv[TN];
#pragma unroll
            for (int i = 0; i < TM; i++) a[i] = As[kk][tr + i];
#pragma unroll
            for (int j = 0; j < TN; j++) bv[j] = Bs[kk][tc + j];
#pragma unroll
            for (int i = 0; i < TM; i++)
#pragma unroll
                for (int j = 0; j < TN; j++) acc[i][j] += a[i] * bv[j];
        }
        __syncthreads();
    }
#pragma unroll
    for (int i = 0; i < TM; i++) {
        int gr = brow + tr + i;
        if (gr >= M) continue;
#pragma unroll
        for (int j = 0; j < TN; j++) {
            int gc = bcol + tc + j;
            if (gc >= N) continue;
            float v = acc[i][j] + bias[gc];
            if (RESID) v += resid[gr * N + gc];
            C[gr * N + gc] = v;
        }
    }
}

// ---------------- key/query projection + phase tables ----------------
// one warp per row; lanes 0..15 -> key planes, lanes 16..31 -> query planes
__global__ void proj_phase_kernel(const float* __restrict__ x,
                                  const float* __restrict__ keyp,
                                  const float* __restrict__ queryp,
                                  const float* __restrict__ setw)
{
    int row = blockIdx.x;
    int lane = threadIdx.x;
    int t = lane & 15;
    const float* W = (lane < 16) ? keyp : queryp;
    const float* xr = x + row * DD;
    float acc = 0.f;
    for (int k = 0; k < DD; k++) acc += xr[k] * W[k * TPJ + t];
    float theta = tanhf(acc) * PI_F;

    // joint (cross-bank) phase: sum over ns for same pp, per half-warp
    float csum = theta;
    csum += __shfl_xor_sync(0xffffffffu, csum, 4);
    csum += __shfl_xor_sync(0xffffffffu, csum, 8);

    // softmax(set_weights)
    float w0 = setw[0], w1 = setw[1], w2 = setw[2], w3 = setw[3];
    float m = fmaxf(fmaxf(w0, w1), fmaxf(w2, w3));
    float e0 = expf(w0 - m), e1 = expf(w1 - m), e2 = expf(w2 - m), e3 = expf(w3 - m);
    float inv = 1.f / (e0 + e1 + e2 + e3);
    float wv[4] = {e0 * inv, e1 * inv, e2 * inv, e3 * inv};

    float s, c;
    sincosf(theta, &s, &c);
    if (lane < 16) {
        g_kph[row * 40 + 2 * t] = c;
        g_kph[row * 40 + 2 * t + 1] = s;
        if (t < 4) {
            float s2, c2;
            sincosf(csum, &s2, &c2);
            g_kph[row * 40 + 2 * (16 + t)] = c2;
            g_kph[row * 40 + 2 * (16 + t) + 1] = s2;
        }
    } else {
        float wq = wv[t >> 2] * 0.2f;   // w[ns] / (NS+1)
        g_qph[row * 40 + 2 * t] = c * wq;
        g_qph[row * 40 + 2 * t + 1] = s * wq;
        if (t < 4) {
            float s2, c2;
            sincosf(csum, &s2, &c2);
            g_qph[row * 40 + 2 * (16 + t)] = c2 * 0.2f;    // cross weight 1/(NS+1)
            g_qph[row * 40 + 2 * (16 + t) + 1] = s2 * 0.2f;
        }
    }
}

// ---------------- positional phase table ----------------
__global__ void posph_kernel(const float* __restrict__ freqs)
{
    int i = blockIdx.x * blockDim.x + threadIdx.x;
    if (i >= LL * PDIM) return;
    int l = i >> 4, p = i & 15;
    float a = ((float)l * freqs[p]) * (2.0f * PI_F);  // match reference fp32 rounding order
    float s, c;
    sincosf(a, &s, &c);
    g_posph[l * 32 + 2 * p] = c;
    g_posph[l * 32 + 2 * p + 1] = s;
}

// ---------------- write-gate (serial tiny scan of jk per batch) ----------------
__global__ void wg_kernel(const float* __restrict__ rscale, const float* __restrict__ rthr,
                          const float* __restrict__ sscale, const float* __restrict__ sbias)
{
    int b = blockIdx.x;
    int lane = threadIdx.x;
    float rs = fminf(fmaxf(rscale[0], 1.f), 20.f);
    float th = fminf(fmaxf(rthr[0], 0.1f), 0.9f);
    float ss = sscale[0], sb = sbias[0];
    float cr = 0.f, ci = 0.f;
    for (int l = 0; l < LL; l++) {
        float mg = (lane < 4) ? sqrtf(cr * cr + ci * ci) : 0.f;  // |km| (exclusive cumsum)
        mg += __shfl_xor_sync(0xffffffffu, mg, 1);
        mg += __shfl_xor_sync(0xffffffffu, mg, 2);
        if (lane == 0) {
            float mag = mg * 0.25f;
            float nres = mag * rsqrtf(fmaxf((float)l, 1.f));
            float sup = 0.5f * (1.f - tanhf(rs * (nres - th)));
            g_wg[b * LL + l] = 1.f / (1.f + expf(-(ss * (sup - 0.5f) + sb)));
        }
        if (lane < 4) {
            cr += g_kph[(b * LL + l) * 40 + 2 * (16 + lane)];
            ci += g_kph[(b * LL + l) * 40 + 2 * (16 + lane) + 1];
        }
    }
}

// ---------------- gate = sigmoid(gelu(hpre) @ g2_w + g2_b) ----------------
__global__ __launch_bounds__(256) void gate_kernel(const float* __restrict__ g2w,
                                                   const float* __restrict__ g2b)
{
    int row = blockIdx.x;
    int tid = threadIdx.x;
    float v = g_hpre[row * HG + tid];
    float ge = 0.5f * v * (1.f + erff(v * 0.70710678118654752f));  // exact gelu
    float p = ge * g2w[tid];
#pragma unroll
    for (int o = 16; o > 0; o >>= 1) p += __shfl_down_sync(0xffffffffu, p, o);
    __shared__ float red[8];
    if ((tid & 31) == 0) red[tid >> 5] = p;
    __syncthreads();
    if (tid == 0) {
        float s = red[0] + red[1] + red[2] + red[3] + red[4] + red[5] + red[6] + red[7];
        g_gate[row] = 1.f / (1.f + expf(-(s + g2b[0])));
    }
}

// ---------------- pass A: per-chunk channel sums ----------------
__global__ __launch_bounds__(512) void chunk_sum_kernel()
{
    int j = blockIdx.x, b = blockIdx.y, d = threadIdx.x;
    int l0 = j * SCH;
    __shared__ float skph[SCH * 40];
    __shared__ float sposp[SCH * 32];
    __shared__ float swg[SCH];
    for (int i = d; i < SCH * 40; i += DD) skph[i] = g_kph[(b * LL + l0) * 40 + i];
    for (int i = d; i < SCH * 32; i += DD) sposp[i] = g_posph[l0 * 32 + i];
    if (d < SCH) swg[d] = g_wg[b * LL + l0 + d];
    __syncthreads();

    float ar[NCHAN], ai[NCHAN];
#pragma unroll
    for (int c = 0; c < NCHAN; c++) { ar[c] = 0.f; ai[c] = 0.f; }

    for (int l = 0; l < SCH; l++) {
        float v = g_V[(b * LL + l0 + l) * DD + d];
        float vg = v * swg[l];
        const float* kp = skph + l * 40;
        const float* pp = sposp + l * 32;
#pragma unroll
        for (int c = 0; c < 20; c++) {
            ar[c] += kp[2 * c] * vg;
            ai[c] += kp[2 * c + 1] * vg;
        }
#pragma unroll
        for (int p = 0; p < 16; p++) {
            ar[20 + p] += pp[2 * p] * v;
            ai[20 + p] += pp[2 * p + 1] * v;
        }
    }
#pragma unroll
    for (int c = 0; c < NCHAN; c++)
        g_S[((b * CCH + j) * NCHAN + c) * DD + d] = make_float2(ar[c], ai[c]);
}

// ---------------- pass B: exclusive prefix over chunks ----------------
__global__ void prefix_kernel()
{
    int id = blockIdx.x * blockDim.x + threadIdx.x;
    if (id >= BB * NCHAN * DD) return;
    int d = id & (DD - 1);
    int c = (id >> 9) % NCHAN;
    int b = id / (NCHAN * DD);
    float2 run = make_float2(0.f, 0.f);
    for (int j = 0; j < CCH; j++) {
        int idx = ((b * CCH + j) * NCHAN + c) * DD + d;
        float2 t = g_S[idx];
        g_S[idx] = run;
        run.x += t.x;
        run.y += t.y;
    }
}

// ---------------- pass C: final scan + retrieval + LayerNorm ----------------
__global__ __launch_bounds__(512) void final_kernel(const float* __restrict__ posw,
                                                    const float* __restrict__ lng,
                                                    const float* __restrict__ lnb)
{
    int j = blockIdx.x, b = blockIdx.y, d = threadIdx.x;
    int l0 = j * SCH;
    __shared__ float skph[SCH * 40];
    __shared__ float sqph[SCH * 40];
    __shared__ float sposp[SCH * 32];
    __shared__ float swg[SCH];
    __shared__ float sgate[SCH];
    __shared__ float redA[16], redB[16];
    __shared__ float smu, srstd;

    for (int i = d; i < SCH * 40; i += DD) {
        skph[i] = g_kph[(b * LL + l0) * 40 + i];
        sqph[i] = g_qph[(b * LL + l0) * 40 + i];
    }
    for (int i = d; i < SCH * 32; i += DD) sposp[i] = g_posph[l0 * 32 + i];
    if (d < SCH) {
        swg[d] = g_wg[b * LL + l0 + d];
        sgate[d] = g_gate[b * LL + l0 + d];
    }
    __syncthreads();

    float spw = 1.f / (1.f + expf(-posw[0]));
    float gam = lng[d], bet = lnb[d];

    float ar[NCHAN], ai[NCHAN];
#pragma unroll
    for (int c = 0; c < NCHAN; c++) {
        float2 t = g_S[((b * CCH + j) * NCHAN + c) * DD + d];
        ar[c] = t.x;
        ai[c] = t.y;
    }

    for (int l = 0; l < SCH; l++) {
        int lg = l0 + l;
        float v = g_V[(b * LL + lg) * DD + d];
        float vg = v * swg[l];
        const float* kp = skph + l * 40;
        const float* qp = sqph + l * 40;
        const float* pp = sposp + l * 32;
        float r1 = 0.f, r2 = 0.f;
#pragma unroll
        for (int c = 0; c < 20; c++) {
            ar[c] += kp[2 * c] * vg;
            ai[c] += kp[2 * c + 1] * vg;
            r1 += ar[c] * qp[2 * c] + ai[c] * qp[2 * c + 1];
        }
#pragma unroll
        for (int p = 0; p < 16; p++) {
            ar[20 + p] += pp[2 * p] * v;
            ai[20 + p] += pp[2 * p + 1] * v;
            r2 += ar[20 + p] * pp[2 * p] + ai[20 + p] * pp[2 * p + 1];
        }
        float gl = sgate[l];
        float y = (gl * r1 + (1.f - gl) * spw * r2) * rsqrtf(4.0f * (float)(lg + 1));

        // block LayerNorm over D=512
        float s1 = y, s2 = y * y;
#pragma unroll
        for (int o = 16; o > 0; o >>= 1) {
            s1 += __shfl_down_sync(0xffffffffu, s1, o);
            s2 += __shfl_down_sync(0xffffffffu, s2, o);
        }
        int wp = d >> 5, ln = d & 31;
        if (ln == 0) { redA[wp] = s1; redB[wp] = s2; }
        __syncthreads();
        if (wp == 0) {
            float a = (ln < 16) ? redA[ln] : 0.f;
            float bb = (ln < 16) ? redB[ln] : 0.f;
#pragma unroll
            for (int o = 16; o > 0; o >>= 1) {
                a += __shfl_down_sync(0xffffffffu, a, o);
                bb += __shfl_down_sync(0xffffffffu, bb, o);
            }
            if (ln == 0) {
                float mu = a * (1.f / (float)DD);
                float var = bb * (1.f / (float)DD) - mu * mu;
                smu = mu;
                srstd = rsqrtf(var + 1e-5f);
            }
        }
        __syncthreads();
        g_yn[(b * LL + lg) * DD + d] = (y - smu) * srstd * gam + bet;
    }
}

// ---------------- launch ----------------
extern "C" void kernel_launch(void* const* d_in, const int* in_sizes, int n_in,
                              void* d_out, int out_size)
{
    const float* x      = (const float*)d_in[0];
    const float* keyp   = (const float*)d_in[1];
    const float* queryp = (const float*)d_in[2];
    const float* v_w    = (const float*)d_in[4];
    const float* v_b    = (const float*)d_in[5];
    const float* ln_g   = (const float*)d_in[6];
    const float* ln_b   = (const float*)d_in[7];
    const float* out_w  = (const float*)d_in[8];
    const float* out_b  = (const float*)d_in[9];
    const float* setw   = (const float*)d_in[10];
    const float* posf   = (const float*)d_in[11];
    const float* posw   = (const float*)d_in[12];
    const float* g1w    = (const float*)d_in[13];
    const float* g1b    = (const float*)d_in[14];
    const float* g2w    = (const float*)d_in[15];
    const float* g2b    = (const float*)d_in[16];
    const float* sscale = (const float*)d_in[19];
    const float* sbias  = (const float*)d_in[20];
    const float* rscale = (const float*)d_in[21];
    const float* rthr   = (const float*)d_in[22];
    float* out = (float*)d_out;

    float *pV, *pH, *pY;
    cudaGetSymbolAddress((void**)&pV, g_V);
    cudaGetSymbolAddress((void**)&pH, g_hpre);
    cudaGetSymbolAddress((void**)&pY, g_yn);

    // front-end GEMMs
    sgemm_kernel<false><<<dim3(DD / 64, RR / 64), 256>>>(x, v_w, v_b, nullptr, pV, RR, DD, DD);
    sgemm_kernel<false><<<dim3(HG / 64, RR / 64), 256>>>(x, g1w, g1b, nullptr, pH, RR, HG, DD);

    // phase tables
    proj_phase_kernel<<<RR, 32>>>(x, keyp, queryp, setw);
    posph_kernel<<<(LL * PDIM + 255) / 256, 256>>>(posf);

    // gates
    wg_kernel<<<BB, 32>>>(rscale, rthr, sscale, sbias);
    gate_kernel<<<RR, HG>>>(g2w, g2b);

    // chunked scan
    chunk_sum_kernel<<<dim3(CCH, BB), DD>>>();
    prefix_kernel<<<(BB * NCHAN * DD + 255) / 256, 256>>>();
    final_kernel<<<dim3(CCH, BB), DD>>>(posw, ln_g, ln_b);

    // output projection + residual
    sgemm_kernel<true><<<dim3(DD / 64, RR / 64), 256>>>(pY, out_w, out_b, x, out, RR, DD, DD);
}

// round 2
// speedup vs baseline: 2.2509x; 2.2509x over previous
#include <cuda_runtime.h>
#include <math.h>

// Problem constants
#define BB 2
#define LL 1024
#define DD 512
#define RR (BB * LL)          // 2048 rows
#define TPJ 16                // total planes (NS*PP)
#define PDIM 16               // positional planes
#define NCHAN 36              // 16 bank + 4 cross + 16 positional
#define CCH 64                // chunks along L
#define SCH 16                // chunk size (CCH*SCH == LL)
#define HG 256                // g1 hidden

#define PI_F 3.14159265358979323846f

// ---------------- device scratch (static; no allocations) ----------------
__device__ float2 g_S[BB * CCH * NCHAN * DD];   // chunk sums -> exclusive prefixes
__device__ float  g_V[RR * DD];                 // V_real = x@v_w + v_b
__device__ float  g_hpre[RR * HG];              // x@g1_w + g1_b (pre-gelu)
__device__ float  g_gate[RR];
__device__ float  g_wg[RR];
__device__ float  g_kph[RR * 40];               // 20 channels x (cos,sin) key phases
__device__ float  g_qph[RR * 40];               // 20 channels x (cos,sin) query phases (weight-scaled)
__device__ float  g_posph[LL * 32];             // 16 channels x (cos,sin)
__device__ float  g_yn[RR * DD];                // layer-normed y

// ---------------- 128x128x8 register-blocked SGEMM ----------------
// C[M,N] = A[M,K] @ B[K,N] + bias[N] (+ resid[M,N])
// Requires M%128==0, N%128==0, K%8==0 (true for all call sites).
template <bool RESID>
__global__ __launch_bounds__(256) void sgemm128(
    const float* __restrict__ A, const float* __restrict__ B,
    const float* __restrict__ bias, const float* __restrict__ resid,
    float* __restrict__ C, int M, int N, int K)
{
    __shared__ float As[8][128];
    __shared__ float Bs[8][128];
    int tid = threadIdx.x;
    int bm = blockIdx.y * 128, bn = blockIdx.x * 128;

    int arow = tid >> 1;            // 0..127
    int acol = (tid & 1) * 4;       // 0 or 4
    int brow = tid >> 5;            // 0..7
    int bcol = (tid & 31) * 4;      // 0..124
    int tr = (tid >> 4) * 8;        // 0..120
    int tc = (tid & 15) * 8;        // 0..120

    float acc[8][8];
#pragma unroll
    for (int i = 0; i < 8; i++)
#pragma unroll
        for (int j = 0; j < 8; j++) acc[i][j] = 0.f;

    const float* Aptr = A + (bm + arow) * K + acol;
    const float* Bptr = B + brow * N + bn + bcol;

    for (int k0 = 0; k0 < K; k0 += 8) {
        float4 av = *(const float4*)(Aptr + k0);
        float4 bv = *(const float4*)(Bptr + k0 * N);
        As[acol + 0][arow] = av.x;
        As[acol + 1][arow] = av.y;
        As[acol + 2][arow] = av.z;
        As[acol + 3][arow] = av.w;
        *(float4*)&Bs[brow][bcol] = bv;
        __syncthreads();
#pragma unroll
        for (int kk = 0; kk < 8; kk++) {
            float a[8], b[8];
            *(float4*)&a[0] = *(const float4*)&As[kk][tr];
            *(float4*)&a[4] = *(const float4*)&As[kk][tr + 4];
            *(float4*)&b[0] = *(const float4*)&Bs[kk][tc];
            *(float4*)&b[4] = *(const float4*)&Bs[kk][tc + 4];
#pragma unroll
            for (int i = 0; i < 8; i++)
#pragma unroll
                for (int j = 0; j < 8; j++) acc[i][j] += a[i] * b[j];
        }
        __syncthreads();
    }

#pragma unroll
    for (int i = 0; i < 8; i++) {
        int gr = bm + tr + i;
#pragma unroll
        for (int j = 0; j < 8; j += 4) {
            int gc = bn + tc + j;
            float4 o;
            o.x = acc[i][j + 0] + bias[gc + 0];
            o.y = acc[i][j + 1] + bias[gc + 1];
            o.z = acc[i][j + 2] + bias[gc + 2];
            o.w = acc[i][j + 3] + bias[gc + 3];
            if (RESID) {
                float4 r = *(const float4*)&resid[gr * N + gc];
                o.x += r.x; o.y += r.y; o.z += r.z; o.w += r.w;
            }
            *(float4*)&C[gr * N + gc] = o;
        }
    }
}

// ---------------- key/query projection + phase tables ----------------
__global__ void proj_phase_kernel(const float* __restrict__ x,
                                  const float* __restrict__ keyp,
                                  const float* __restrict__ queryp,
                                  const float* __restrict__ setw)
{
    int row = blockIdx.x;
    int lane = threadIdx.x;
    int t = lane & 15;
    const float* W = (lane < 16) ? keyp : queryp;
    const float* xr = x + row * DD;
    float acc = 0.f;
    for (int k = 0; k < DD; k++) acc += xr[k] * W[k * TPJ + t];
    float theta = tanhf(acc) * PI_F;

    float csum = theta;
    csum += __shfl_xor_sync(0xffffffffu, csum, 4);
    csum += __shfl_xor_sync(0xffffffffu, csum, 8);

    float w0 = setw[0], w1 = setw[1], w2 = setw[2], w3 = setw[3];
    float m = fmaxf(fmaxf(w0, w1), fmaxf(w2, w3));
    float e0 = expf(w0 - m), e1 = expf(w1 - m), e2 = expf(w2 - m), e3 = expf(w3 - m);
    float inv = 1.f / (e0 + e1 + e2 + e3);
    float wv[4] = {e0 * inv, e1 * inv, e2 * inv, e3 * inv};

    float s, c;
    sincosf(theta, &s, &c);
    if (lane < 16) {
        g_kph[row * 40 + 2 * t] = c;
        g_kph[row * 40 + 2 * t + 1] = s;
        if (t < 4) {
            float s2, c2;
            sincosf(csum, &s2, &c2);
            g_kph[row * 40 + 2 * (16 + t)] = c2;
            g_kph[row * 40 + 2 * (16 + t) + 1] = s2;
        }
    } else {
        float wq = wv[t >> 2] * 0.2f;
        g_qph[row * 40 + 2 * t] = c * wq;
        g_qph[row * 40 + 2 * t + 1] = s * wq;
        if (t < 4) {
            float s2, c2;
            sincosf(csum, &s2, &c2);
            g_qph[row * 40 + 2 * (16 + t)] = c2 * 0.2f;
            g_qph[row * 40 + 2 * (16 + t) + 1] = s2 * 0.2f;
        }
    }
}

// ---------------- positional phase table ----------------
__global__ void posph_kernel(const float* __restrict__ freqs)
{
    int i = blockIdx.x * blockDim.x + threadIdx.x;
    if (i >= LL * PDIM) return;
    int l = i >> 4, p = i & 15;
    float a = ((float)l * freqs[p]) * (2.0f * PI_F);
    float s, c;
    sincosf(a, &s, &c);
    g_posph[l * 32 + 2 * p] = c;
    g_posph[l * 32 + 2 * p + 1] = s;
}

// ---------------- write-gate: PARALLEL block scan of jk over L ----------------
// One block of 1024 threads per batch; scans 8 float components (4 complex planes).
__global__ __launch_bounds__(1024) void wg_scan_kernel(
    const float* __restrict__ rscale, const float* __restrict__ rthr,
    const float* __restrict__ sscale, const float* __restrict__ sbias)
{
    int b = blockIdx.x;
    int l = threadIdx.x;
    int lane = l & 31, wp = l >> 5;

    float v[8], own[8];
    const float* src = g_kph + (b * LL + l) * 40 + 32;
#pragma unroll
    for (int c = 0; c < 8; c++) { v[c] = src[c]; own[c] = v[c]; }

    // warp-level inclusive scan
#pragma unroll
    for (int off = 1; off < 32; off <<= 1) {
#pragma unroll
        for (int c = 0; c < 8; c++) {
            float t = __shfl_up_sync(0xffffffffu, v[c], off);
            if (lane >= off) v[c] += t;
        }
    }

    __shared__ float wtot[32][8];
    if (lane == 31) {
#pragma unroll
        for (int c = 0; c < 8; c++) wtot[wp][c] = v[c];
    }
    __syncthreads();
    if (wp == 0) {
        float w[8];
#pragma unroll
        for (int c = 0; c < 8; c++) w[c] = wtot[lane][c];
#pragma unroll
        for (int off = 1; off < 32; off <<= 1) {
#pragma unroll
            for (int c = 0; c < 8; c++) {
                float t = __shfl_up_sync(0xffffffffu, w[c], off);
                if (lane >= off) w[c] += t;
            }
        }
#pragma unroll
        for (int c = 0; c < 8; c++) wtot[lane][c] = w[c];
    }
    __syncthreads();

    // exclusive prefix at position l = warp_offset + warp_inclusive - own
    float mag = 0.f;
#pragma unroll
    for (int p = 0; p < 4; p++) {
        float woc = (wp > 0) ? wtot[wp - 1][2 * p] : 0.f;
        float wos = (wp > 0) ? wtot[wp - 1][2 * p + 1] : 0.f;
        float cr = woc + v[2 * p] - own[2 * p];
        float ci = wos + v[2 * p + 1] - own[2 * p + 1];
        mag += sqrtf(cr * cr + ci * ci);
    }
    mag *= 0.25f;

    float rs = fminf(fmaxf(rscale[0], 1.f), 20.f);
    float th = fminf(fmaxf(rthr[0], 0.1f), 0.9f);
    float nres = mag * rsqrtf(fmaxf((float)l, 1.f));
    float sup = 0.5f * (1.f - tanhf(rs * (nres - th)));
    g_wg[b * LL + l] = 1.f / (1.f + expf(-(sscale[0] * (sup - 0.5f) + sbias[0])));
}

// ---------------- gate = sigmoid(gelu(hpre) @ g2_w + g2_b) ----------------
__global__ __launch_bounds__(256) void gate_kernel(const float* __restrict__ g2w,
                                                   const float* __restrict__ g2b)
{
    int row = blockIdx.x;
    int tid = threadIdx.x;
    float v = g_hpre[row * HG + tid];
    float ge = 0.5f * v * (1.f + erff(v * 0.70710678118654752f));
    float p = ge * g2w[tid];
#pragma unroll
    for (int o = 16; o > 0; o >>= 1) p += __shfl_down_sync(0xffffffffu, p, o);
    __shared__ float red[8];
    if ((tid & 31) == 0) red[tid >> 5] = p;
    __syncthreads();
    if (tid == 0) {
        float s = red[0] + red[1] + red[2] + red[3] + red[4] + red[5] + red[6] + red[7];
        g_gate[row] = 1.f / (1.f + expf(-(s + g2b[0])));
    }
}

// ---------------- pass A: per-chunk channel sums ----------------
__global__ __launch_bounds__(512) void chunk_sum_kernel()
{
    int j = blockIdx.x, b = blockIdx.y, d = threadIdx.x;
    int l0 = j * SCH;
    __shared__ float skph[SCH * 40];
    __shared__ float sposp[SCH * 32];
    __shared__ float swg[SCH];
    for (int i = d; i < SCH * 40; i += DD) skph[i] = g_kph[(b * LL + l0) * 40 + i];
    for (int i = d; i < SCH * 32; i += DD) sposp[i] = g_posph[l0 * 32 + i];
    if (d < SCH) swg[d] = g_wg[b * LL + l0 + d];
    __syncthreads();

    float ar[NCHAN], ai[NCHAN];
#pragma unroll
    for (int c = 0; c < NCHAN; c++) { ar[c] = 0.f; ai[c] = 0.f; }

    for (int l = 0; l < SCH; l++) {
        float v = g_V[(b * LL + l0 + l) * DD + d];
        float vg = v * swg[l];
        const float* kp = skph + l * 40;
        const float* pp = sposp + l * 32;
#pragma unroll
        for (int c = 0; c < 20; c++) {
            ar[c] += kp[2 * c] * vg;
            ai[c] += kp[2 * c + 1] * vg;
        }
#pragma unroll
        for (int p = 0; p < 16; p++) {
            ar[20 + p] += pp[2 * p] * v;
            ai[20 + p] += pp[2 * p + 1] * v;
        }
    }
#pragma unroll
    for (int c = 0; c < NCHAN; c++)
        g_S[((b * CCH + j) * NCHAN + c) * DD + d] = make_float2(ar[c], ai[c]);
}

// ---------------- pass B: exclusive prefix over chunks ----------------
__global__ void prefix_kernel()
{
    int id = blockIdx.x * blockDim.x + threadIdx.x;
    if (id >= BB * NCHAN * DD) return;
    int d = id & (DD - 1);
    int c = (id >> 9) % NCHAN;
    int b = id / (NCHAN * DD);
    float2 run = make_float2(0.f, 0.f);
    for (int j = 0; j < CCH; j++) {
        int idx = ((b * CCH + j) * NCHAN + c) * DD + d;
        float2 t = g_S[idx];
        g_S[idx] = run;
        run.x += t.x;
        run.y += t.y;
    }
}

// ---------------- pass C: final scan + retrieval + LayerNorm ----------------
__global__ __launch_bounds__(512) void final_kernel(const float* __restrict__ posw,
                                                    const float* __restrict__ lng,
                                                    const float* __restrict__ lnb)
{
    int j = blockIdx.x, b = blockIdx.y, d = threadIdx.x;
    int l0 = j * SCH;
    __shared__ float skph[SCH * 40];
    __shared__ float sqph[SCH * 40];
    __shared__ float sposp[SCH * 32];
    __shared__ float swg[SCH];
    __shared__ float sgate[SCH];
    __shared__ float redA[16], redB[16];
    __shared__ float smu, srstd;

    for (int i = d; i < SCH * 40; i += DD) {
        skph[i] = g_kph[(b * LL + l0) * 40 + i];
        sqph[i] = g_qph[(b * LL + l0) * 40 + i];
    }
    for (int i = d; i < SCH * 32; i += DD) sposp[i] = g_posph[l0 * 32 + i];
    if (d < SCH) {
        swg[d] = g_wg[b * LL + l0 + d];
        sgate[d] = g_gate[b * LL + l0 + d];
    }
    __syncthreads();

    float spw = 1.f / (1.f + expf(-posw[0]));
    float gam = lng[d], bet = lnb[d];

    float ar[NCHAN], ai[NCHAN];
#pragma unroll
    for (int c = 0; c < NCHAN; c++) {
        float2 t = g_S[((b * CCH + j) * NCHAN + c) * DD + d];
        ar[c] = t.x;
        ai[c] = t.y;
    }

    for (int l = 0; l < SCH; l++) {
        int lg = l0 + l;
        float v = g_V[(b * LL + lg) * DD + d];
        float vg = v * swg[l];
        const float* kp = skph + l * 40;
        const float* qp = sqph + l * 40;
        const float* pp = sposp + l * 32;
        float r1 = 0.f, r2 = 0.f;
#pragma unroll
        for (int c = 0; c < 20; c++) {
            ar[c] += kp[2 * c] * vg;
            ai[c] += kp[2 * c + 1] * vg;
            r1 += ar[c] * qp[2 * c] + ai[c] * qp[2 * c + 1];
        }
#pragma unroll
        for (int p = 0; p < 16; p++) {
            ar[20 + p] += pp[2 * p] * v;
            ai[20 + p] += pp[2 * p + 1] * v;
            r2 += ar[20 + p] * pp[2 * p] + ai[20 + p] * pp[2 * p + 1];
        }
        float gl = sgate[l];
        float y = (gl * r1 + (1.f - gl) * spw * r2) * rsqrtf(4.0f * (float)(lg + 1));

        float s1 = y, s2 = y * y;
#pragma unroll
        for (int o = 16; o > 0; o >>= 1) {
            s1 += __shfl_down_sync(0xffffffffu, s1, o);
            s2 += __shfl_down_sync(0xffffffffu, s2, o);
        }
        int wp = d >> 5, ln = d & 31;
        if (ln == 0) { redA[wp] = s1; redB[wp] = s2; }
        __syncthreads();
        if (wp == 0) {
            float a = (ln < 16) ? redA[ln] : 0.f;
            float bb = (ln < 16) ? redB[ln] : 0.f;
#pragma unroll
            for (int o = 16; o > 0; o >>= 1) {
                a += __shfl_down_sync(0xffffffffu, a, o);
                bb += __shfl_down_sync(0xffffffffu, bb, o);
            }
            if (ln == 0) {
                float mu = a * (1.f / (float)DD);
                float var = bb * (1.f / (float)DD) - mu * mu;
                smu = mu;
                srstd = rsqrtf(var + 1e-5f);
            }
        }
        __syncthreads();
        g_yn[(b * LL + lg) * DD + d] = (y - smu) * srstd * gam + bet;
    }
}

// ---------------- launch ----------------
extern "C" void kernel_launch(void* const* d_in, const int* in_sizes, int n_in,
                              void* d_out, int out_size)
{
    const float* x      = (const float*)d_in[0];
    const float* keyp   = (const float*)d_in[1];
    const float* queryp = (const float*)d_in[2];
    const float* v_w    = (const float*)d_in[4];
    const float* v_b    = (const float*)d_in[5];
    const float* ln_g   = (const float*)d_in[6];
    const float* ln_b   = (const float*)d_in[7];
    const float* out_w  = (const float*)d_in[8];
    const float* out_b  = (const float*)d_in[9];
    const float* setw   = (const float*)d_in[10];
    const float* posf   = (const float*)d_in[11];
    const float* posw   = (const float*)d_in[12];
    const float* g1w    = (const float*)d_in[13];
    const float* g1b    = (const float*)d_in[14];
    const float* g2w    = (const float*)d_in[15];
    const float* g2b    = (const float*)d_in[16];
    const float* sscale = (const float*)d_in[19];
    const float* sbias  = (const float*)d_in[20];
    const float* rscale = (const float*)d_in[21];
    const float* rthr   = (const float*)d_in[22];
    float* out = (float*)d_out;

    float *pV, *pH, *pY;
    cudaGetSymbolAddress((void**)&pV, g_V);
    cudaGetSymbolAddress((void**)&pH, g_hpre);
    cudaGetSymbolAddress((void**)&pY, g_yn);

    // front-end GEMMs
    sgemm128<false><<<dim3(DD / 128, RR / 128), 256>>>(x, v_w, v_b, nullptr, pV, RR, DD, DD);
    sgemm128<false><<<dim3(HG / 128, RR / 128), 256>>>(x, g1w, g1b, nullptr, pH, RR, HG, DD);

    // phase tables
    proj_phase_kernel<<<RR, 32>>>(x, keyp, queryp, setw);
    posph_kernel<<<(LL * PDIM + 255) / 256, 256>>>(posf);

    // gates
    wg_scan_kernel<<<BB, LL>>>(rscale, rthr, sscale, sbias);
    gate_kernel<<<RR, HG>>>(g2w, g2b);

    // chunked scan
    chunk_sum_kernel<<<dim3(CCH, BB), DD>>>();
    prefix_kernel<<<(BB * NCHAN * DD + 255) / 256, 256>>>();
    final_kernel<<<dim3(CCH, BB), DD>>>(posw, ln_g, ln_b);

    // output projection + residual
    sgemm128<true><<<dim3(DD / 128, RR / 128), 256>>>(pY, out_w, out_b, x, out, RR, DD, DD);
}

// round 4
// speedup vs baseline: 5.7268x; 2.5442x over previous
#include <cuda_runtime.h>
#include <cuda_bf16.h>
#include <math.h>
#include <stdint.h>

// Problem constants
#define BB 2
#define LL 1024
#define DD 512
#define RR (BB * LL)          // 2048 rows
#define TPJ 16                // total planes (NS*PP)
#define PDIM 16               // positional planes
#define NCHAN 36              // 16 bank + 4 cross + 16 positional
#define CCH 64                // chunks along L
#define SCH 16                // chunk size
#define HG 256                // g1 hidden

#define PI_F 3.14159265358979323846f

// ===================== base-ISA tensor helpers (sm_80+ PTX, compute_103-safe) =====
__device__ __forceinline__ uint32_t smem_u32(const void* p) {
    uint32_t a;
    asm("{ .reg .u64 t; cvta.to.shared.u64 t, %1; cvt.u32.u64 %0, t; }" : "=r"(a) : "l"(p));
    return a;
}
__device__ __forceinline__ void ldsm_x4(uint32_t* r, uint32_t addr) {
    asm volatile("ldmatrix.sync.aligned.m8n8.x4.shared.b16 {%0,%1,%2,%3}, [%4];"
                 : "=r"(r[0]), "=r"(r[1]), "=r"(r[2]), "=r"(r[3]) : "r"(addr));
}
__device__ __forceinline__ void mma16816(float* d, const uint32_t* a, const uint32_t* b) {
    asm volatile("mma.sync.aligned.m16n8k16.row.col.f32.bf16.bf16.f32 "
                 "{%0,%1,%2,%3}, {%4,%5,%6,%7}, {%8,%9}, {%0,%1,%2,%3};"
                 : "+f"(d[0]), "+f"(d[1]), "+f"(d[2]), "+f"(d[3])
                 : "r"(a[0]), "r"(a[1]), "r"(a[2]), "r"(a[3]), "r"(b[0]), "r"(b[1]));
}
#define CP_ASYNC16(sm, gp) \
    asm volatile("cp.async.cg.shared.global [%0], [%1], 16;" :: "r"(sm), "l"(gp))
#define CP_COMMIT() asm volatile("cp.async.commit_group;" ::: "memory")
#define CP_WAIT1() asm volatile("cp.async.wait_group 1;" ::: "memory")
#define CP_WAIT0() asm volatile("cp.async.wait_group 0;" ::: "memory")

// ===================== device scratch =====================
__device__ float2 g_S[BB * CCH * NCHAN * DD];
__device__ float  g_V[RR * DD];
__device__ float  g_hpre[RR * HG];
__device__ float  g_gate[RR];
__device__ float  g_wg[RR];
__device__ float  g_kph[RR * 40];
__device__ float  g_qph[RR * 40];
__device__ float  g_posph[LL * 32];
__device__ __nv_bfloat16 g_xh[RR * DD], g_xl[RR * DD];
__device__ __nv_bfloat16 g_ynh[RR * DD], g_ynl[RR * DD];
__device__ __nv_bfloat16 g_wvh[DD * DD], g_wvl[DD * DD];
__device__ __nv_bfloat16 g_woh[DD * DD], g_wol[DD * DD];
__device__ __nv_bfloat16 g_wgh[HG * DD], g_wgl[HG * DD];

// ===================== conversion kernels =====================
__global__ void convert_x_kernel(const float* __restrict__ x,
                                 __nv_bfloat16* __restrict__ xh,
                                 __nv_bfloat16* __restrict__ xl)
{
    int i = blockIdx.x * blockDim.x + threadIdx.x;
    float4 v = ((const float4*)x)[i];
    float f[4] = {v.x, v.y, v.z, v.w};
    __nv_bfloat16 h[4], l[4];
#pragma unroll
    for (int k = 0; k < 4; k++) {
        h[k] = __float2bfloat16_rn(f[k]);
        l[k] = __float2bfloat16_rn(f[k] - __bfloat162float(h[k]));
    }
    ((__nv_bfloat162*)xh)[2 * i]     = __nv_bfloat162(h[0], h[1]);
    ((__nv_bfloat162*)xh)[2 * i + 1] = __nv_bfloat162(h[2], h[3]);
    ((__nv_bfloat162*)xl)[2 * i]     = __nv_bfloat162(l[0], l[1]);
    ((__nv_bfloat162*)xl)[2 * i + 1] = __nv_bfloat162(l[2], l[3]);
}

// W[K][N] fp32 -> Wt_hi/Wt_lo [N][K] bf16 (transpose + split)
__global__ void convert_wT_kernel(const float* __restrict__ W,
                                  __nv_bfloat16* __restrict__ Th,
                                  __nv_bfloat16* __restrict__ Tl, int K, int N)
{
    __shared__ float t[32][33];
    int n0 = blockIdx.x * 32, k0 = blockIdx.y * 32;
    int tx = threadIdx.x, ty = threadIdx.y;  // 32 x 8
#pragma unroll
    for (int i = 0; i < 32; i += 8) t[ty + i][tx] = W[(k0 + ty + i) * N + n0 + tx];
    __syncthreads();
#pragma unroll
    for (int i = 0; i < 32; i += 8) {
        float v = t[tx][ty + i];
        __nv_bfloat16 h = __float2bfloat16_rn(v);
        Th[(n0 + ty + i) * K + k0 + tx] = h;
        Tl[(n0 + ty + i) * K + k0 + tx] = __float2bfloat16_rn(v - __bfloat162float(h));
    }
}

// ===================== mma.sync GEMM (bf16 hi/lo split) =====================
// C[M,Ntot] = (Ah+Al)[M,512] @ (Bh+Bl)[N,512]^T + bias (+ resid)
// CTA tile 128x64, warp tile 32x32, BK=32, 2-stage cp.async pipeline.
// smem stage layout (bf16 elems, pitch 40 = 80B): Ah[128*40] Al[128*40] Bh[64*40] Bl[64*40]
#define ST_EL 15360
#define GM_SMEM_BYTES (2 * ST_EL * 2)

template <bool RESID>
__global__ void __launch_bounds__(256) gemm_mma_kernel(
    const __nv_bfloat16* __restrict__ Ah, const __nv_bfloat16* __restrict__ Al,
    const __nv_bfloat16* __restrict__ Bh, const __nv_bfloat16* __restrict__ Bl,
    const float* __restrict__ bias, const float* __restrict__ resid,
    float* __restrict__ C, int Ntot)
{
    extern __shared__ __nv_bfloat16 smem[];
    const int tid = threadIdx.x, lane = tid & 31, wid = tid >> 5;
    const int wm = (wid >> 1) * 32, wn = (wid & 1) * 32;
    const int bm = blockIdx.y * 128, bn = blockIdx.x * 64;
    const int K = 512;

    uint32_t sbase = smem_u32(smem);

    // gmem coords for loader
    int arow = tid >> 2, aq = tid & 3;            // A: 2 iters of 128 rows
    int brow = tid >> 2, bq = tid & 3;            // B: 64 rows in one iter

    auto load_chunk = [&](int c, int s) {
        uint32_t st = sbase + s * ST_EL * 2;
        int k0 = c * 32;
        // Ah / Al : 128 rows x 32 cols  (2 units/thread each)
#pragma unroll
        for (int i = 0; i < 2; i++) {
            int r = arow + i * 64;
            uint32_t so = st + (r * 40 + aq * 8) * 2;
            CP_ASYNC16(so, Ah + (bm + r) * K + k0 + aq * 8);
            CP_ASYNC16(so + ST_EL, Al + (bm + r) * K + k0 + aq * 8);  // note: +ST_EL bytes? no!
        }
        // Bh / Bl : 64 rows x 32 cols (1 unit/thread each)
        {
            uint32_t so = st + (10240 + brow * 40 + bq * 8) * 2;
            CP_ASYNC16(so, Bh + (bn + brow) * K + k0 + bq * 8);
            CP_ASYNC16(so + 2560 * 2, Bl + (bn + brow) * K + k0 + bq * 8);
        }
    };
    // fix Al offset: Al lives at +5120 elems within stage
    // (re-implemented inline below to avoid the erroneous lambda math)

    auto load_chunk2 = [&](int c, int s) {
        uint32_t st = sbase + s * ST_EL * 2;
        int k0 = c * 32;
#pragma unroll
        for (int i = 0; i < 2; i++) {
            int r = arow + i * 64;
            uint32_t so = st + (r * 40 + aq * 8) * 2;
            CP_ASYNC16(so, Ah + (bm + r) * K + k0 + aq * 8);
            CP_ASYNC16(so + 5120 * 2, Al + (bm + r) * K + k0 + aq * 8);
        }
        {
            uint32_t so = st + (10240 + brow * 40 + bq * 8) * 2;
            CP_ASYNC16(so, Bh + (bn + brow) * K + k0 + bq * 8);
            CP_ASYNC16(so + 2560 * 2, Bl + (bn + brow) * K + k0 + bq * 8);
        }
    };
    (void)load_chunk;

    float acc[2][4][4];
#pragma unroll
    for (int mt = 0; mt < 2; mt++)
#pragma unroll
        for (int nt = 0; nt < 4; nt++)
#pragma unroll
            for (int e = 0; e < 4; e++) acc[mt][nt][e] = 0.f;

    load_chunk2(0, 0);
    CP_COMMIT();

    // ldmatrix lane address components
    int a_row = (lane & 7) + ((lane >> 3) & 1) * 8;      // within 16
    int a_k16 = ((lane >> 4) & 1) * 16;                  // byte offset for k8 group
    int b_row = (lane & 7) + ((lane >> 4) & 1) * 8;
    int b_k16 = ((lane >> 3) & 1) * 16;

    for (int c = 0; c < 16; c++) {
        int s = c & 1;
        if (c + 1 < 16) { load_chunk2(c + 1, s ^ 1); CP_COMMIT(); CP_WAIT1(); }
        else CP_WAIT0();
        __syncthreads();

        uint32_t st = sbase + s * ST_EL * 2;
#pragma unroll
        for (int ks = 0; ks < 2; ks++) {
            uint32_t aH[8], aL[8], bH[8], bL[8];
#pragma unroll
            for (int mt = 0; mt < 2; mt++) {
                int row = wm + mt * 16 + a_row;
                uint32_t ad = st + (row * 40) * 2 + ks * 32 + a_k16;
                ldsm_x4(aH + mt * 4, ad);
                ldsm_x4(aL + mt * 4, ad + 5120 * 2);
            }
#pragma unroll
            for (int np = 0; np < 2; np++) {
                int row = wn + np * 16 + b_row;
                uint32_t bd = st + (10240 + row * 40) * 2 + ks * 32 + b_k16;
                ldsm_x4(bH + np * 4, bd);
                ldsm_x4(bL + np * 4, bd + 2560 * 2);
            }
#pragma unroll
            for (int mt = 0; mt < 2; mt++)
#pragma unroll
                for (int nt = 0; nt < 4; nt++) {
                    uint32_t* bh = bH + (nt >> 1) * 4 + (nt & 1) * 2;
                    uint32_t* bl = bL + (nt >> 1) * 4 + (nt & 1) * 2;
                    mma16816(acc[mt][nt], aH + mt * 4, bh);
                    mma16816(acc[mt][nt], aH + mt * 4, bl);
                    mma16816(acc[mt][nt], aL + mt * 4, bh);
                }
        }
        __syncthreads();
    }

    // epilogue: direct stores with bias (+resid)
#pragma unroll
    for (int mt = 0; mt < 2; mt++)
#pragma unroll
        for (int nt = 0; nt < 4; nt++) {
            int col = bn + wn + nt * 8 + (lane & 3) * 2;
            float b0 = bias[col], b1 = bias[col + 1];
#pragma unroll
            for (int h = 0; h < 2; h++) {
                int row = bm + wm + mt * 16 + (lane >> 2) + h * 8;
                float2 o;
                o.x = acc[mt][nt][h * 2 + 0] + b0;
                o.y = acc[mt][nt][h * 2 + 1] + b1;
                if (RESID) {
                    float2 rr = *(const float2*)&resid[row * Ntot + col];
                    o.x += rr.x; o.y += rr.y;
                }
                *(float2*)&C[row * Ntot + col] = o;
            }
        }
}

// ===================== phase / gate / scan kernels =====================
__global__ void proj_phase_kernel(const float* __restrict__ x,
                                  const float* __restrict__ keyp,
                                  const float* __restrict__ queryp,
                                  const float* __restrict__ setw)
{
    int row = blockIdx.x;
    int lane = threadIdx.x;
    int t = lane & 15;
    const float* W = (lane < 16) ? keyp : queryp;
    const float* xr = x + row * DD;
    float acc = 0.f;
    for (int k = 0; k < DD; k++) acc += xr[k] * W[k * TPJ + t];
    float theta = tanhf(acc) * PI_F;

    float csum = theta;
    csum += __shfl_xor_sync(0xffffffffu, csum, 4);
    csum += __shfl_xor_sync(0xffffffffu, csum, 8);

    float w0 = setw[0], w1 = setw[1], w2 = setw[2], w3 = setw[3];
    float m = fmaxf(fmaxf(w0, w1), fmaxf(w2, w3));
    float e0 = expf(w0 - m), e1 = expf(w1 - m), e2 = expf(w2 - m), e3 = expf(w3 - m);
    float inv = 1.f / (e0 + e1 + e2 + e3);
    float wv[4] = {e0 * inv, e1 * inv, e2 * inv, e3 * inv};

    float s, c;
    sincosf(theta, &s, &c);
    if (lane < 16) {
        g_kph[row * 40 + 2 * t] = c;
        g_kph[row * 40 + 2 * t + 1] = s;
        if (t < 4) {
            float s2, c2;
            sincosf(csum, &s2, &c2);
            g_kph[row * 40 + 2 * (16 + t)] = c2;
            g_kph[row * 40 + 2 * (16 + t) + 1] = s2;
        }
    } else {
        float wq = wv[t >> 2] * 0.2f;
        g_qph[row * 40 + 2 * t] = c * wq;
        g_qph[row * 40 + 2 * t + 1] = s * wq;
        if (t < 4) {
            float s2, c2;
            sincosf(csum, &s2, &c2);
            g_qph[row * 40 + 2 * (16 + t)] = c2 * 0.2f;
            g_qph[row * 40 + 2 * (16 + t) + 1] = s2 * 0.2f;
        }
    }
}

__global__ void posph_kernel(const float* __restrict__ freqs)
{
    int i = blockIdx.x * blockDim.x + threadIdx.x;
    if (i >= LL * PDIM) return;
    int l = i >> 4, p = i & 15;
    float a = ((float)l * freqs[p]) * (2.0f * PI_F);
    float s, c;
    sincosf(a, &s, &c);
    g_posph[l * 32 + 2 * p] = c;
    g_posph[l * 32 + 2 * p + 1] = s;
}

__global__ __launch_bounds__(1024) void wg_scan_kernel(
    const float* __restrict__ rscale, const float* __restrict__ rthr,
    const float* __restrict__ sscale, const float* __restrict__ sbias)
{
    int b = blockIdx.x;
    int l = threadIdx.x;
    int lane = l & 31, wp = l >> 5;

    float v[8], own[8];
    const float* src = g_kph + (b * LL + l) * 40 + 32;
#pragma unroll
    for (int c = 0; c < 8; c++) { v[c] = src[c]; own[c] = v[c]; }
#pragma unroll
    for (int off = 1; off < 32; off <<= 1) {
#pragma unroll
        for (int c = 0; c < 8; c++) {
            float t = __shfl_up_sync(0xffffffffu, v[c], off);
            if (lane >= off) v[c] += t;
        }
    }
    __shared__ float wtot[32][8];
    if (lane == 31) {
#pragma unroll
        for (int c = 0; c < 8; c++) wtot[wp][c] = v[c];
    }
    __syncthreads();
    if (wp == 0) {
        float w[8];
#pragma unroll
        for (int c = 0; c < 8; c++) w[c] = wtot[lane][c];
#pragma unroll
        for (int off = 1; off < 32; off <<= 1) {
#pragma unroll
            for (int c = 0; c < 8; c++) {
                float t = __shfl_up_sync(0xffffffffu, w[c], off);
                if (lane >= off) w[c] += t;
            }
        }
#pragma unroll
        for (int c = 0; c < 8; c++) wtot[lane][c] = w[c];
    }
    __syncthreads();

    float mag = 0.f;
#pragma unroll
    for (int p = 0; p < 4; p++) {
        float woc = (wp > 0) ? wtot[wp - 1][2 * p] : 0.f;
        float wos = (wp > 0) ? wtot[wp - 1][2 * p + 1] : 0.f;
        float cr = woc + v[2 * p] - own[2 * p];
        float ci = wos + v[2 * p + 1] - own[2 * p + 1];
        mag += sqrtf(cr * cr + ci * ci);
    }
    mag *= 0.25f;

    float rs = fminf(fmaxf(rscale[0], 1.f), 20.f);
    float th = fminf(fmaxf(rthr[0], 0.1f), 0.9f);
    float nres = mag * rsqrtf(fmaxf((float)l, 1.f));
    float sup = 0.5f * (1.f - tanhf(rs * (nres - th)));
    g_wg[b * LL + l] = 1.f / (1.f + expf(-(sscale[0] * (sup - 0.5f) + sbias[0])));
}

__global__ __launch_bounds__(256) void gate_kernel(const float* __restrict__ g2w,
                                                   const float* __restrict__ g2b)
{
    int row = blockIdx.x;
    int tid = threadIdx.x;
    float v = g_hpre[row * HG + tid];
    float ge = 0.5f * v * (1.f + erff(v * 0.70710678118654752f));
    float p = ge * g2w[tid];
#pragma unroll
    for (int o = 16; o > 0; o >>= 1) p += __shfl_down_sync(0xffffffffu, p, o);
    __shared__ float red[8];
    if ((tid & 31) == 0) red[tid >> 5] = p;
    __syncthreads();
    if (tid == 0) {
        float s = red[0] + red[1] + red[2] + red[3] + red[4] + red[5] + red[6] + red[7];
        g_gate[row] = 1.f / (1.f + expf(-(s + g2b[0])));
    }
}

__global__ __launch_bounds__(512) void chunk_sum_kernel()
{
    int j = blockIdx.x, b = blockIdx.y, d = threadIdx.x;
    int l0 = j * SCH;
    __shared__ float skph[SCH * 40];
    __shared__ float sposp[SCH * 32];
    __shared__ float swg[SCH];
    for (int i = d; i < SCH * 40; i += DD) skph[i] = g_kph[(b * LL + l0) * 40 + i];
    for (int i = d; i < SCH * 32; i += DD) sposp[i] = g_posph[l0 * 32 + i];
    if (d < SCH) swg[d] = g_wg[b * LL + l0 + d];
    __syncthreads();

    float ar[NCHAN], ai[NCHAN];
#pragma unroll
    for (int c = 0; c < NCHAN; c++) { ar[c] = 0.f; ai[c] = 0.f; }

    for (int l = 0; l < SCH; l++) {
        float v = g_V[(b * LL + l0 + l) * DD + d];
        float vg = v * swg[l];
        const float* kp = skph + l * 40;
        const float* pp = sposp + l * 32;
#pragma unroll
        for (int c = 0; c < 20; c++) {
            ar[c] += kp[2 * c] * vg;
            ai[c] += kp[2 * c + 1] * vg;
        }
#pragma unroll
        for (int p = 0; p < 16; p++) {
            ar[20 + p] += pp[2 * p] * v;
            ai[20 + p] += pp[2 * p + 1] * v;
        }
    }
#pragma unroll
    for (int c = 0; c < NCHAN; c++)
        g_S[((b * CCH + j) * NCHAN + c) * DD + d] = make_float2(ar[c], ai[c]);
}

__global__ void prefix_kernel()
{
    int id = blockIdx.x * blockDim.x + threadIdx.x;
    if (id >= BB * NCHAN * DD) return;
    int d = id & (DD - 1);
    int c = (id >> 9) % NCHAN;
    int b = id / (NCHAN * DD);
    float2 run = make_float2(0.f, 0.f);
    for (int j = 0; j < CCH; j++) {
        int idx = ((b * CCH + j) * NCHAN + c) * DD + d;
        float2 t = g_S[idx];
        g_S[idx] = run;
        run.x += t.x;
        run.y += t.y;
    }
}

__global__ __launch_bounds__(512) void final_kernel(const float* __restrict__ posw,
                                                    const float* __restrict__ lng,
                                                    const float* __restrict__ lnb)
{
    int j = blockIdx.x, b = blockIdx.y, d = threadIdx.x;
    int l0 = j * SCH;
    __shared__ float skph[SCH * 40];
    __shared__ float sqph[SCH * 40];
    __shared__ float sposp[SCH * 32];
    __shared__ float swg[SCH];
    __shared__ float sgate[SCH];
    __shared__ float redA[16], redB[16];
    __shared__ float smu, srstd;

    for (int i = d; i < SCH * 40; i += DD) {
        skph[i] = g_kph[(b * LL + l0) * 40 + i];
        sqph[i] = g_qph[(b * LL + l0) * 40 + i];
    }
    for (int i = d; i < SCH * 32; i += DD) sposp[i] = g_posph[l0 * 32 + i];
    if (d < SCH) {
        swg[d] = g_wg[b * LL + l0 + d];
        sgate[d] = g_gate[b * LL + l0 + d];
    }
    __syncthreads();

    float spw = 1.f / (1.f + expf(-posw[0]));
    float gam = lng[d], bet = lnb[d];

    float ar[NCHAN], ai[NCHAN];
#pragma unroll
    for (int c = 0; c < NCHAN; c++) {
        float2 t = g_S[((b * CCH + j) * NCHAN + c) * DD + d];
        ar[c] = t.x;
        ai[c] = t.y;
    }

    for (int l = 0; l < SCH; l++) {
        int lg = l0 + l;
        float v = g_V[(b * LL + lg) * DD + d];
        float vg = v * swg[l];
        const float* kp = skph + l * 40;
        const float* qp = sqph + l * 40;
        const float* pp = sposp + l * 32;
        float r1 = 0.f, r2 = 0.f;
#pragma unroll
        for (int c = 0; c < 20; c++) {
            ar[c] += kp[2 * c] * vg;
            ai[c] += kp[2 * c + 1] * vg;
            r1 += ar[c] * qp[2 * c] + ai[c] * qp[2 * c + 1];
        }
#pragma unroll
        for (int p = 0; p < 16; p++) {
            ar[20 + p] += pp[2 * p] * v;
            ai[20 + p] += pp[2 * p + 1] * v;
            r2 += ar[20 + p] * pp[2 * p] + ai[20 + p] * pp[2 * p + 1];
        }
        float gl = sgate[l];
        float y = (gl * r1 + (1.f - gl) * spw * r2) * rsqrtf(4.0f * (float)(lg + 1));

        float s1 = y, s2 = y * y;
#pragma unroll
        for (int o = 16; o > 0; o >>= 1) {
            s1 += __shfl_down_sync(0xffffffffu, s1, o);
            s2 += __shfl_down_sync(0xffffffffu, s2, o);
        }
        int wp = d >> 5, ln = d & 31;
        if (ln == 0) { redA[wp] = s1; redB[wp] = s2; }
        __syncthreads();
        if (wp == 0) {
            float a = (ln < 16) ? redA[ln] : 0.f;
            float bb = (ln < 16) ? redB[ln] : 0.f;
#pragma unroll
            for (int o = 16; o > 0; o >>= 1) {
                a += __shfl_down_sync(0xffffffffu, a, o);
                bb += __shfl_down_sync(0xffffffffu, bb, o);
            }
            if (ln == 0) {
                float mu = a * (1.f / (float)DD);
                float var = bb * (1.f / (float)DD) - mu * mu;
                smu = mu;
                srstd = rsqrtf(var + 1e-5f);
            }
        }
        __syncthreads();
        float yn = (y - smu) * srstd * gam + bet;
        __nv_bfloat16 h = __float2bfloat16_rn(yn);
        int idx = (b * LL + lg) * DD + d;
        g_ynh[idx] = h;
        g_ynl[idx] = __float2bfloat16_rn(yn - __bfloat162float(h));
    }
}

// ===================== launch =====================
extern "C" void kernel_launch(void* const* d_in, const int* in_sizes, int n_in,
                              void* d_out, int out_size)
{
    const float* x      = (const float*)d_in[0];
    const float* keyp   = (const float*)d_in[1];
    const float* queryp = (const float*)d_in[2];
    const float* v_w    = (const float*)d_in[4];
    const float* v_b    = (const float*)d_in[5];
    const float* ln_g   = (const float*)d_in[6];
    const float* ln_b   = (const float*)d_in[7];
    const float* out_w  = (const float*)d_in[8];
    const float* out_b  = (const float*)d_in[9];
    const float* setw   = (const float*)d_in[10];
    const float* posf   = (const float*)d_in[11];
    const float* posw   = (const float*)d_in[12];
    const float* g1w    = (const float*)d_in[13];
    const float* g1b    = (const float*)d_in[14];
    const float* g2w    = (const float*)d_in[15];
    const float* g2b    = (const float*)d_in[16];
    const float* sscale = (const float*)d_in[19];
    const float* sbias  = (const float*)d_in[20];
    const float* rscale = (const float*)d_in[21];
    const float* rthr   = (const float*)d_in[22];
    float* out = (float*)d_out;

    cudaFuncSetAttribute(gemm_mma_kernel<false>,
                         cudaFuncAttributeMaxDynamicSharedMemorySize, GM_SMEM_BYTES);
    cudaFuncSetAttribute(gemm_mma_kernel<true>,
                         cudaFuncAttributeMaxDynamicSharedMemorySize, GM_SMEM_BYTES);

    float *pV, *pH;
    __nv_bfloat16 *pXh, *pXl, *pYh, *pYl, *pWvh, *pWvl, *pWoh, *pWol, *pWgh, *pWgl;
    cudaGetSymbolAddress((void**)&pV, g_V);
    cudaGetSymbolAddress((void**)&pH, g_hpre);
    cudaGetSymbolAddress((void**)&pXh, g_xh);
    cudaGetSymbolAddress((void**)&pXl, g_xl);
    cudaGetSymbolAddress((void**)&pYh, g_ynh);
    cudaGetSymbolAddress((void**)&pYl, g_ynl);
    cudaGetSymbolAddress((void**)&pWvh, g_wvh);
    cudaGetSymbolAddress((void**)&pWvl, g_wvl);
    cudaGetSymbolAddress((void**)&pWoh, g_woh);
    cudaGetSymbolAddress((void**)&pWol, g_wol);
    cudaGetSymbolAddress((void**)&pWgh, g_wgh);
    cudaGetSymbolAddress((void**)&pWgl, g_wgl);

    // conversions
    convert_x_kernel<<<RR * DD / 4 / 256, 256>>>(x, pXh, pXl);
    convert_wT_kernel<<<dim3(DD / 32, DD / 32), dim3(32, 8)>>>(v_w, pWvh, pWvl, DD, DD);
    convert_wT_kernel<<<dim3(HG / 32, DD / 32), dim3(32, 8)>>>(g1w, pWgh, pWgl, DD, HG);
    convert_wT_kernel<<<dim3(DD / 32, DD / 32), dim3(32, 8)>>>(out_w, pWoh, pWol, DD, DD);

    // front-end GEMMs on tensor pipe (mma.sync)
    gemm_mma_kernel<false><<<dim3(DD / 64, RR / 128), 256, GM_SMEM_BYTES>>>(
        pXh, pXl, pWvh, pWvl, v_b, nullptr, pV, DD);
    gemm_mma_kernel<false><<<dim3(HG / 64, RR / 128), 256, GM_SMEM_BYTES>>>(
        pXh, pXl, pWgh, pWgl, g1b, nullptr, pH, HG);

    // phase tables
    proj_phase_kernel<<<RR, 32>>>(x, keyp, queryp, setw);
    posph_kernel<<<(LL * PDIM + 255) / 256, 256>>>(posf);

    // gates
    wg_scan_kernel<<<BB, LL>>>(rscale, rthr, sscale, sbias);
    gate_kernel<<<RR, HG>>>(g2w, g2b);

    // chunked scan
    chunk_sum_kernel<<<dim3(CCH, BB), DD>>>();
    prefix_kernel<<<(BB * NCHAN * DD + 255) / 256, 256>>>();
    final_kernel<<<dim3(CCH, BB), DD>>>(posw, ln_g, ln_b);

    // output projection + residual
    gemm_mma_kernel<true><<<dim3(DD / 64, RR / 128), 256, GM_SMEM_BYTES>>>(
        pYh, pYl, pWoh, pWol, out_b, x, out, DD);
}

// round 5
// speedup vs baseline: 7.3140x; 1.2771x over previous
#include <cuda_runtime.h>
#include <cuda_bf16.h>
#include <math.h>
#include <stdint.h>

// Problem constants
#define BB 2
#define LL 1024
#define DD 512
#define RR (BB * LL)          // 2048 rows
#define TPJ 16                // total planes (NS*PP)
#define PDIM 16               // positional planes
#define NCHAN 36              // 16 bank + 4 cross + 16 positional
#define CCH 64                // chunks along L
#define SCH 16                // chunk size
#define HG 256                // g1 hidden

#define PI_F 3.14159265358979323846f

// ===================== base-ISA tensor helpers =====================
__device__ __forceinline__ uint32_t smem_u32(const void* p) {
    uint32_t a;
    asm("{ .reg .u64 t; cvta.to.shared.u64 t, %1; cvt.u32.u64 %0, t; }" : "=r"(a) : "l"(p));
    return a;
}
__device__ __forceinline__ void ldsm_x4(uint32_t* r, uint32_t addr) {
    asm volatile("ldmatrix.sync.aligned.m8n8.x4.shared.b16 {%0,%1,%2,%3}, [%4];"
                 : "=r"(r[0]), "=r"(r[1]), "=r"(r[2]), "=r"(r[3]) : "r"(addr));
}
__device__ __forceinline__ void mma16816(float* d, const uint32_t* a, const uint32_t* b) {
    asm volatile("mma.sync.aligned.m16n8k16.row.col.f32.bf16.bf16.f32 "
                 "{%0,%1,%2,%3}, {%4,%5,%6,%7}, {%8,%9}, {%0,%1,%2,%3};"
                 : "+f"(d[0]), "+f"(d[1]), "+f"(d[2]), "+f"(d[3])
                 : "r"(a[0]), "r"(a[1]), "r"(a[2]), "r"(a[3]), "r"(b[0]), "r"(b[1]));
}
#define CP_ASYNC16(sm, gp) \
    asm volatile("cp.async.cg.shared.global [%0], [%1], 16;" :: "r"(sm), "l"(gp))
#define CP_COMMIT() asm volatile("cp.async.commit_group;" ::: "memory")
#define CP_WAIT1() asm volatile("cp.async.wait_group 1;" ::: "memory")
#define CP_WAIT0() asm volatile("cp.async.wait_group 0;" ::: "memory")

// ===================== device scratch =====================
__device__ float2 g_S[BB * CCH * NCHAN * DD];
__device__ float  g_V[RR * DD];
__device__ float  g_hpre[RR * HG];
__device__ float  g_gate[RR];
__device__ float  g_wg[RR];
__device__ float  g_kph[RR * 40];
__device__ float  g_qph[RR * 40];
__device__ float  g_posph[LL * 32];
__device__ __nv_bfloat16 g_xh[RR * DD], g_xl[RR * DD];
__device__ __nv_bfloat16 g_ynh[RR * DD], g_ynl[RR * DD];
__device__ __nv_bfloat16 g_wvh[DD * DD], g_wvl[DD * DD];
__device__ __nv_bfloat16 g_woh[DD * DD], g_wol[DD * DD];
__device__ __nv_bfloat16 g_wgh[HG * DD], g_wgl[HG * DD];

// ===================== side-stream infra (static init: pre-checkpoint) =====
__global__ void warm_kernel() {}
struct SideStreams {
    cudaStream_t s1, s2;
    cudaEvent_t evFork, evConv, evB, evGate;
    SideStreams() {
        cudaStreamCreateWithFlags(&s1, cudaStreamNonBlocking);
        cudaStreamCreateWithFlags(&s2, cudaStreamNonBlocking);
        cudaEventCreateWithFlags(&evFork, cudaEventDisableTiming);
        cudaEventCreateWithFlags(&evConv, cudaEventDisableTiming);
        cudaEventCreateWithFlags(&evB, cudaEventDisableTiming);
        cudaEventCreateWithFlags(&evGate, cudaEventDisableTiming);
        warm_kernel<<<1, 32, 0, s1>>>();
        warm_kernel<<<1, 32, 0, s2>>>();
        cudaDeviceSynchronize();
    }
};
static SideStreams g_ss;

// ===================== conversion kernels =====================
__global__ void convert_x_kernel(const float* __restrict__ x)
{
    int i = blockIdx.x * blockDim.x + threadIdx.x;
    float4 v = ((const float4*)x)[i];
    float f[4] = {v.x, v.y, v.z, v.w};
    __nv_bfloat16 h[4], l[4];
#pragma unroll
    for (int k = 0; k < 4; k++) {
        h[k] = __float2bfloat16_rn(f[k]);
        l[k] = __float2bfloat16_rn(f[k] - __bfloat162float(h[k]));
    }
    ((__nv_bfloat162*)g_xh)[2 * i]     = __nv_bfloat162(h[0], h[1]);
    ((__nv_bfloat162*)g_xh)[2 * i + 1] = __nv_bfloat162(h[2], h[3]);
    ((__nv_bfloat162*)g_xl)[2 * i]     = __nv_bfloat162(l[0], l[1]);
    ((__nv_bfloat162*)g_xl)[2 * i + 1] = __nv_bfloat162(l[2], l[3]);
}

// all three weights: W[512][N] fp32 -> [N][512] bf16 hi/lo, z selects tensor
__global__ void convert_w_all(const float* __restrict__ vw,
                              const float* __restrict__ g1w,
                              const float* __restrict__ ow)
{
    __shared__ float t[32][33];
    int z = blockIdx.z;
    const float* W;
    __nv_bfloat16 *Th, *Tl;
    int N;
    if (z == 0)      { W = vw;  Th = g_wvh; Tl = g_wvl; N = DD; }
    else if (z == 1) { W = ow;  Th = g_woh; Tl = g_wol; N = DD; }
    else             { W = g1w; Th = g_wgh; Tl = g_wgl; N = HG; }
    int n0 = blockIdx.x * 32, k0 = blockIdx.y * 32;
    if (n0 >= N) return;
    int tx = threadIdx.x, ty = threadIdx.y;  // 32 x 8
#pragma unroll
    for (int i = 0; i < 32; i += 8) t[ty + i][tx] = W[(k0 + ty + i) * N + n0 + tx];
    __syncthreads();
#pragma unroll
    for (int i = 0; i < 32; i += 8) {
        float v = t[tx][ty + i];
        __nv_bfloat16 h = __float2bfloat16_rn(v);
        Th[(n0 + ty + i) * DD + k0 + tx] = h;
        Tl[(n0 + ty + i) * DD + k0 + tx] = __float2bfloat16_rn(v - __bfloat162float(h));
    }
}

// ===================== mma.sync GEMM (bf16 hi/lo split) =====================
#define ST_EL 15360
#define GM_SMEM_BYTES (2 * ST_EL * 2)

template <bool RESID>
__global__ void __launch_bounds__(256) gemm_mma_kernel(
    const __nv_bfloat16* __restrict__ Ah, const __nv_bfloat16* __restrict__ Al,
    const __nv_bfloat16* __restrict__ Bh, const __nv_bfloat16* __restrict__ Bl,
    const float* __restrict__ bias, const float* __restrict__ resid,
    float* __restrict__ C, int Ntot)
{
    extern __shared__ __nv_bfloat16 smem[];
    const int tid = threadIdx.x, lane = tid & 31, wid = tid >> 5;
    const int wm = (wid >> 1) * 32, wn = (wid & 1) * 32;
    const int bm = blockIdx.y * 128, bn = blockIdx.x * 64;
    const int K = 512;

    uint32_t sbase = smem_u32(smem);
    int arow = tid >> 2, aq = tid & 3;
    int brow = tid >> 2, bq = tid & 3;

    auto load_chunk = [&](int c, int s) {
        uint32_t st = sbase + s * ST_EL * 2;
        int k0 = c * 32;
#pragma unroll
        for (int i = 0; i < 2; i++) {
            int r = arow + i * 64;
            uint32_t so = st + (r * 40 + aq * 8) * 2;
            CP_ASYNC16(so, Ah + (bm + r) * K + k0 + aq * 8);
            CP_ASYNC16(so + 5120 * 2, Al + (bm + r) * K + k0 + aq * 8);
        }
        {
            uint32_t so = st + (10240 + brow * 40 + bq * 8) * 2;
            CP_ASYNC16(so, Bh + (bn + brow) * K + k0 + bq * 8);
            CP_ASYNC16(so + 2560 * 2, Bl + (bn + brow) * K + k0 + bq * 8);
        }
    };

    float acc[2][4][4];
#pragma unroll
    for (int mt = 0; mt < 2; mt++)
#pragma unroll
        for (int nt = 0; nt < 4; nt++)
#pragma unroll
            for (int e = 0; e < 4; e++) acc[mt][nt][e] = 0.f;

    load_chunk(0, 0);
    CP_COMMIT();

    int a_row = (lane & 7) + ((lane >> 3) & 1) * 8;
    int a_k16 = ((lane >> 4) & 1) * 16;
    int b_row = (lane & 7) + ((lane >> 4) & 1) * 8;
    int b_k16 = ((lane >> 3) & 1) * 16;

    for (int c = 0; c < 16; c++) {
        int s = c & 1;
        if (c + 1 < 16) { load_chunk(c + 1, s ^ 1); CP_COMMIT(); CP_WAIT1(); }
        else CP_WAIT0();
        __syncthreads();

        uint32_t st = sbase + s * ST_EL * 2;
#pragma unroll
        for (int ks = 0; ks < 2; ks++) {
            uint32_t aH[8], aL[8], bH[8], bL[8];
#pragma unroll
            for (int mt = 0; mt < 2; mt++) {
                int row = wm + mt * 16 + a_row;
                uint32_t ad = st + (row * 40) * 2 + ks * 32 + a_k16;
                ldsm_x4(aH + mt * 4, ad);
                ldsm_x4(aL + mt * 4, ad + 5120 * 2);
            }
#pragma unroll
            for (int np = 0; np < 2; np++) {
                int row = wn + np * 16 + b_row;
                uint32_t bd = st + (10240 + row * 40) * 2 + ks * 32 + b_k16;
                ldsm_x4(bH + np * 4, bd);
                ldsm_x4(bL + np * 4, bd + 2560 * 2);
            }
#pragma unroll
            for (int mt = 0; mt < 2; mt++)
#pragma unroll
                for (int nt = 0; nt < 4; nt++) {
                    uint32_t* bh = bH + (nt >> 1) * 4 + (nt & 1) * 2;
                    uint32_t* bl = bL + (nt >> 1) * 4 + (nt & 1) * 2;
                    mma16816(acc[mt][nt], aH + mt * 4, bh);
                    mma16816(acc[mt][nt], aH + mt * 4, bl);
                    mma16816(acc[mt][nt], aL + mt * 4, bh);
                }
        }
        __syncthreads();
    }

#pragma unroll
    for (int mt = 0; mt < 2; mt++)
#pragma unroll
        for (int nt = 0; nt < 4; nt++) {
            int col = bn + wn + nt * 8 + (lane & 3) * 2;
            float b0 = bias[col], b1 = bias[col + 1];
#pragma unroll
            for (int h = 0; h < 2; h++) {
                int row = bm + wm + mt * 16 + (lane >> 2) + h * 8;
                float2 o;
                o.x = acc[mt][nt][h * 2 + 0] + b0;
                o.y = acc[mt][nt][h * 2 + 1] + b1;
                if (RESID) {
                    float2 rr = *(const float2*)&resid[row * Ntot + col];
                    o.x += rr.x; o.y += rr.y;
                }
                *(float2*)&C[row * Ntot + col] = o;
            }
        }
}

// ===================== phase / gate / scan kernels =====================
// 8 warps per block, one row per warp
__global__ __launch_bounds__(256) void proj_phase_kernel(
    const float* __restrict__ x, const float* __restrict__ keyp,
    const float* __restrict__ queryp, const float* __restrict__ setw)
{
    int row = blockIdx.x * 8 + (threadIdx.x >> 5);
    int lane = threadIdx.x & 31;
    int t = lane & 15;
    const float* W = (lane < 16) ? keyp : queryp;
    const float* xr = x + row * DD;
    float acc = 0.f;
    for (int k = 0; k < DD; k++) acc += xr[k] * W[k * TPJ + t];
    float theta = tanhf(acc) * PI_F;

    float csum = theta;
    csum += __shfl_xor_sync(0xffffffffu, csum, 4);
    csum += __shfl_xor_sync(0xffffffffu, csum, 8);

    float w0 = setw[0], w1 = setw[1], w2 = setw[2], w3 = setw[3];
    float m = fmaxf(fmaxf(w0, w1), fmaxf(w2, w3));
    float e0 = expf(w0 - m), e1 = expf(w1 - m), e2 = expf(w2 - m), e3 = expf(w3 - m);
    float inv = 1.f / (e0 + e1 + e2 + e3);
    float wv[4] = {e0 * inv, e1 * inv, e2 * inv, e3 * inv};

    float s, c;
    sincosf(theta, &s, &c);
    if (lane < 16) {
        g_kph[row * 40 + 2 * t] = c;
        g_kph[row * 40 + 2 * t + 1] = s;
        if (t < 4) {
            float s2, c2;
            sincosf(csum, &s2, &c2);
            g_kph[row * 40 + 2 * (16 + t)] = c2;
            g_kph[row * 40 + 2 * (16 + t) + 1] = s2;
        }
    } else {
        float wq = wv[t >> 2] * 0.2f;
        g_qph[row * 40 + 2 * t] = c * wq;
        g_qph[row * 40 + 2 * t + 1] = s * wq;
        if (t < 4) {
            float s2, c2;
            sincosf(csum, &s2, &c2);
            g_qph[row * 40 + 2 * (16 + t)] = c2 * 0.2f;
            g_qph[row * 40 + 2 * (16 + t) + 1] = s2 * 0.2f;
        }
    }
}

__global__ void posph_kernel(const float* __restrict__ freqs)
{
    int i = blockIdx.x * blockDim.x + threadIdx.x;
    if (i >= LL * PDIM) return;
    int l = i >> 4, p = i & 15;
    float a = ((float)l * freqs[p]) * (2.0f * PI_F);
    float s, c;
    sincosf(a, &s, &c);
    g_posph[l * 32 + 2 * p] = c;
    g_posph[l * 32 + 2 * p + 1] = s;
}

__global__ __launch_bounds__(1024) void wg_scan_kernel(
    const float* __restrict__ rscale, const float* __restrict__ rthr,
    const float* __restrict__ sscale, const float* __restrict__ sbias)
{
    int b = blockIdx.x;
    int l = threadIdx.x;
    int lane = l & 31, wp = l >> 5;

    float v[8], own[8];
    const float* src = g_kph + (b * LL + l) * 40 + 32;
#pragma unroll
    for (int c = 0; c < 8; c++) { v[c] = src[c]; own[c] = v[c]; }
#pragma unroll
    for (int off = 1; off < 32; off <<= 1) {
#pragma unroll
        for (int c = 0; c < 8; c++) {
            float t = __shfl_up_sync(0xffffffffu, v[c], off);
            if (lane >= off) v[c] += t;
        }
    }
    __shared__ float wtot[32][8];
    if (lane == 31) {
#pragma unroll
        for (int c = 0; c < 8; c++) wtot[wp][c] = v[c];
    }
    __syncthreads();
    if (wp == 0) {
        float w[8];
#pragma unroll
        for (int c = 0; c < 8; c++) w[c] = wtot[lane][c];
#pragma unroll
        for (int off = 1; off < 32; off <<= 1) {
#pragma unroll
            for (int c = 0; c < 8; c++) {
                float t = __shfl_up_sync(0xffffffffu, w[c], off);
                if (lane >= off) w[c] += t;
            }
        }
#pragma unroll
        for (int c = 0; c < 8; c++) wtot[lane][c] = w[c];
    }
    __syncthreads();

    float mag = 0.f;
#pragma unroll
    for (int p = 0; p < 4; p++) {
        float woc = (wp > 0) ? wtot[wp - 1][2 * p] : 0.f;
        float wos = (wp > 0) ? wtot[wp - 1][2 * p + 1] : 0.f;
        float cr = woc + v[2 * p] - own[2 * p];
        float ci = wos + v[2 * p + 1] - own[2 * p + 1];
        mag += sqrtf(cr * cr + ci * ci);
    }
    mag *= 0.25f;

    float rs = fminf(fmaxf(rscale[0], 1.f), 20.f);
    float th = fminf(fmaxf(rthr[0], 0.1f), 0.9f);
    float nres = mag * rsqrtf(fmaxf((float)l, 1.f));
    float sup = 0.5f * (1.f - tanhf(rs * (nres - th)));
    g_wg[b * LL + l] = 1.f / (1.f + expf(-(sscale[0] * (sup - 0.5f) + sbias[0])));
}

__global__ __launch_bounds__(256) void gate_kernel(const float* __restrict__ g2w,
                                                   const float* __restrict__ g2b)
{
    int row = blockIdx.x;
    int tid = threadIdx.x;
    float v = g_hpre[row * HG + tid];
    float ge = 0.5f * v * (1.f + erff(v * 0.70710678118654752f));
    float p = ge * g2w[tid];
#pragma unroll
    for (int o = 16; o > 0; o >>= 1) p += __shfl_down_sync(0xffffffffu, p, o);
    __shared__ float red[8];
    if ((tid & 31) == 0) red[tid >> 5] = p;
    __syncthreads();
    if (tid == 0) {
        float s = red[0] + red[1] + red[2] + red[3] + red[4] + red[5] + red[6] + red[7];
        g_gate[row] = 1.f / (1.f + expf(-(s + g2b[0])));
    }
}

__global__ __launch_bounds__(512) void chunk_sum_kernel()
{
    int j = blockIdx.x, b = blockIdx.y, d = threadIdx.x;
    int l0 = j * SCH;
    __shared__ float skph[SCH * 40];
    __shared__ float sposp[SCH * 32];
    __shared__ float swg[SCH];
    for (int i = d; i < SCH * 40; i += DD) skph[i] = g_kph[(b * LL + l0) * 40 + i];
    for (int i = d; i < SCH * 32; i += DD) sposp[i] = g_posph[l0 * 32 + i];
    if (d < SCH) swg[d] = g_wg[b * LL + l0 + d];
    __syncthreads();

    float ar[NCHAN], ai[NCHAN];
#pragma unroll
    for (int c = 0; c < NCHAN; c++) { ar[c] = 0.f; ai[c] = 0.f; }

    for (int l = 0; l < SCH; l++) {
        float v = g_V[(b * LL + l0 + l) * DD + d];
        float vg = v * swg[l];
        const float* kp = skph + l * 40;
        const float* pp = sposp + l * 32;
#pragma unroll
        for (int c = 0; c < 20; c++) {
            ar[c] += kp[2 * c] * vg;
            ai[c] += kp[2 * c + 1] * vg;
        }
#pragma unroll
        for (int p = 0; p < 16; p++) {
            ar[20 + p] += pp[2 * p] * v;
            ai[20 + p] += pp[2 * p + 1] * v;
        }
    }
#pragma unroll
    for (int c = 0; c < NCHAN; c++)
        g_S[((b * CCH + j) * NCHAN + c) * DD + d] = make_float2(ar[c], ai[c]);
}

__global__ void prefix_kernel()
{
    int id = blockIdx.x * blockDim.x + threadIdx.x;
    if (id >= BB * NCHAN * DD) return;
    int d = id & (DD - 1);
    int c = (id >> 9) % NCHAN;
    int b = id / (NCHAN * DD);
    float2 run = make_float2(0.f, 0.f);
    for (int j = 0; j < CCH; j++) {
        int idx = ((b * CCH + j) * NCHAN + c) * DD + d;
        float2 t = g_S[idx];
        g_S[idx] = run;
        run.x += t.x;
        run.y += t.y;
    }
}

// final scan + retrieval; LN via smem row buffer + warp-per-row
__global__ __launch_bounds__(512) void final_kernel(const float* __restrict__ posw,
                                                    const float* __restrict__ lng,
                                                    const float* __restrict__ lnb)
{
    int j = blockIdx.x, b = blockIdx.y, d = threadIdx.x;
    int l0 = j * SCH;
    __shared__ float skph[SCH * 40];
    __shared__ float sqph[SCH * 40];
    __shared__ float sposp[SCH * 32];
    __shared__ float swg[SCH];
    __shared__ float sgate[SCH];
    __shared__ float sy[SCH][DD];

    for (int i = d; i < SCH * 40; i += DD) {
        skph[i] = g_kph[(b * LL + l0) * 40 + i];
        sqph[i] = g_qph[(b * LL + l0) * 40 + i];
    }
    for (int i = d; i < SCH * 32; i += DD) sposp[i] = g_posph[l0 * 32 + i];
    if (d < SCH) {
        swg[d] = g_wg[b * LL + l0 + d];
        sgate[d] = g_gate[b * LL + l0 + d];
    }
    __syncthreads();

    float spw = 1.f / (1.f + expf(-posw[0]));

    float ar[NCHAN], ai[NCHAN];
#pragma unroll
    for (int c = 0; c < NCHAN; c++) {
        float2 t = g_S[((b * CCH + j) * NCHAN + c) * DD + d];
        ar[c] = t.x;
        ai[c] = t.y;
    }

    for (int l = 0; l < SCH; l++) {
        int lg = l0 + l;
        float v = g_V[(b * LL + lg) * DD + d];
        float vg = v * swg[l];
        const float* kp = skph + l * 40;
        const float* qp = sqph + l * 40;
        const float* pp = sposp + l * 32;
        float r1 = 0.f, r2 = 0.f;
#pragma unroll
        for (int c = 0; c < 20; c++) {
            ar[c] += kp[2 * c] * vg;
            ai[c] += kp[2 * c + 1] * vg;
            r1 += ar[c] * qp[2 * c] + ai[c] * qp[2 * c + 1];
        }
#pragma unroll
        for (int p = 0; p < 16; p++) {
            ar[20 + p] += pp[2 * p] * v;
            ai[20 + p] += pp[2 * p + 1] * v;
            r2 += ar[20 + p] * pp[2 * p] + ai[20 + p] * pp[2 * p + 1];
        }
        float gl = sgate[l];
        sy[l][d] = (gl * r1 + (1.f - gl) * spw * r2) * rsqrtf(4.0f * (float)(lg + 1));
    }
    __syncthreads();

    // LayerNorm: one warp per row (16 warps, 16 rows)
    {
        int w = d >> 5, ln = d & 31;
        float vals[16];
        float s1 = 0.f, s2 = 0.f;
#pragma unroll
        for (int k = 0; k < 16; k++) {
            float t = sy[w][ln + k * 32];
            vals[k] = t;
            s1 += t;
            s2 += t * t;
        }
#pragma unroll
        for (int o = 16; o > 0; o >>= 1) {
            s1 += __shfl_xor_sync(0xffffffffu, s1, o);
            s2 += __shfl_xor_sync(0xffffffffu, s2, o);
        }
        float mu = s1 * (1.f / (float)DD);
        float var = s2 * (1.f / (float)DD) - mu * mu;
        float rstd = rsqrtf(var + 1e-5f);
        int base = (b * LL + l0 + w) * DD;
#pragma unroll
        for (int k = 0; k < 16; k++) {
            int d2 = ln + k * 32;
            float yn = (vals[k] - mu) * rstd * lng[d2] + lnb[d2];
            __nv_bfloat16 h = __float2bfloat16_rn(yn);
            g_ynh[base + d2] = h;
            g_ynl[base + d2] = __float2bfloat16_rn(yn - __bfloat162float(h));
        }
    }
}

// ===================== launch =====================
extern "C" void kernel_launch(void* const* d_in, const int* in_sizes, int n_in,
                              void* d_out, int out_size)
{
    const float* x      = (const float*)d_in[0];
    const float* keyp   = (const float*)d_in[1];
    const float* queryp = (const float*)d_in[2];
    const float* v_w    = (const float*)d_in[4];
    const float* v_b    = (const float*)d_in[5];
    const float* ln_g   = (const float*)d_in[6];
    const float* ln_b   = (const float*)d_in[7];
    const float* out_w  = (const float*)d_in[8];
    const float* out_b  = (const float*)d_in[9];
    const float* setw   = (const float*)d_in[10];
    const float* posf   = (const float*)d_in[11];
    const float* posw   = (const float*)d_in[12];
    const float* g1w    = (const float*)d_in[13];
    const float* g1b    = (const float*)d_in[14];
    const float* g2w    = (const float*)d_in[15];
    const float* g2b    = (const float*)d_in[16];
    const float* sscale = (const float*)d_in[19];
    const float* sbias  = (const float*)d_in[20];
    const float* rscale = (const float*)d_in[21];
    const float* rthr   = (const float*)d_in[22];
    float* out = (float*)d_out;

    cudaFuncSetAttribute(gemm_mma_kernel<false>,
                         cudaFuncAttributeMaxDynamicSharedMemorySize, GM_SMEM_BYTES);
    cudaFuncSetAttribute(gemm_mma_kernel<true>,
                         cudaFuncAttributeMaxDynamicSharedMemorySize, GM_SMEM_BYTES);

    float *pV, *pH;
    __nv_bfloat16 *pXh, *pXl, *pYh, *pYl, *pWvh, *pWvl, *pWoh, *pWol, *pWgh, *pWgl;
    cudaGetSymbolAddress((void**)&pV, g_V);
    cudaGetSymbolAddress((void**)&pH, g_hpre);
    cudaGetSymbolAddress((void**)&pXh, g_xh);
    cudaGetSymbolAddress((void**)&pXl, g_xl);
    cudaGetSymbolAddress((void**)&pYh, g_ynh);
    cudaGetSymbolAddress((void**)&pYl, g_ynl);
    cudaGetSymbolAddress((void**)&pWvh, g_wvh);
    cudaGetSymbolAddress((void**)&pWvl, g_wvl);
    cudaGetSymbolAddress((void**)&pWoh, g_woh);
    cudaGetSymbolAddress((void**)&pWol, g_wol);
    cudaGetSymbolAddress((void**)&pWgh, g_wgh);
    cudaGetSymbolAddress((void**)&pWgl, g_wgl);

    // fork side streams off the main (captured) stream
    cudaEventRecord(g_ss.evFork, 0);
    cudaStreamWaitEvent(g_ss.s1, g_ss.evFork, 0);

    // ---- chain B (s1): phases + write gate ----
    proj_phase_kernel<<<RR / 8, 256, 0, g_ss.s1>>>(x, keyp, queryp, setw);
    posph_kernel<<<(LL * PDIM + 255) / 256, 256, 0, g_ss.s1>>>(posf);
    wg_scan_kernel<<<BB, LL, 0, g_ss.s1>>>(rscale, rthr, sscale, sbias);
    cudaEventRecord(g_ss.evB, g_ss.s1);

    // ---- chain A (s0): converts + V gemm ----
    convert_x_kernel<<<RR * DD / 4 / 256, 256>>>(x);
    convert_w_all<<<dim3(16, 16, 3), dim3(32, 8)>>>(v_w, g1w, out_w);
    cudaEventRecord(g_ss.evConv, 0);
    cudaStreamWaitEvent(g_ss.s2, g_ss.evConv, 0);

    gemm_mma_kernel<false><<<dim3(DD / 64, RR / 128), 256, GM_SMEM_BYTES>>>(
        pXh, pXl, pWvh, pWvl, v_b, nullptr, pV, DD);

    // ---- chain C (s2): H gemm + gate ----
    gemm_mma_kernel<false><<<dim3(HG / 64, RR / 128), 256, GM_SMEM_BYTES, g_ss.s2>>>(
        pXh, pXl, pWgh, pWgl, g1b, nullptr, pH, HG);
    gate_kernel<<<RR, HG, 0, g_ss.s2>>>(g2w, g2b);
    cudaEventRecord(g_ss.evGate, g_ss.s2);

    // ---- join + scan chain on s0 ----
    cudaStreamWaitEvent(0, g_ss.evB, 0);
    chunk_sum_kernel<<<dim3(CCH, BB), DD>>>();
    prefix_kernel<<<(BB * NCHAN * DD + 255) / 256, 256>>>();
    cudaStreamWaitEvent(0, g_ss.evGate, 0);
    final_kernel<<<dim3(CCH, BB), DD>>>(posw, ln_g, ln_b);

    // output projection + residual
    gemm_mma_kernel<true><<<dim3(DD / 64, RR / 128), 256, GM_SMEM_BYTES>>>(
        pYh, pYl, pWoh, pWol, out_b, x, out, DD);
}